// round 2
// baseline (speedup 1.0000x reference)
#include <cuda_runtime.h>

#define N_NODES 50000
#define N_EDGES 1600000
#define IN_DIM 6
#define H 64

// Scratch (device globals — no runtime allocation allowed)
__device__ float g_agg1[N_NODES * IN_DIM];
__device__ float g_cnt [N_NODES];
__device__ float g_z   [N_NODES * H];
__device__ float g_agg2[N_NODES * H];

// --- vector reductions (sm_90+ PTX) ---
__device__ __forceinline__ void red_add_v2(float* p, float a, float b) {
    asm volatile("red.global.add.v2.f32 [%0], {%1, %2};"
                 :: "l"(p), "f"(a), "f"(b) : "memory");
}
__device__ __forceinline__ void red_add_v4(float* p, float4 v) {
    asm volatile("red.global.add.v4.f32 [%0], {%1, %2, %3, %4};"
                 :: "l"(p), "f"(v.x), "f"(v.y), "f"(v.z), "f"(v.w) : "memory");
}

// Zero all accumulators (graph replays => must re-zero every launch)
__global__ void k_zero() {
    int i = blockIdx.x * blockDim.x + threadIdx.x;
    if (i < N_NODES * H)       g_agg2[i] = 0.0f;
    if (i < N_NODES * IN_DIM)  g_agg1[i] = 0.0f;
    if (i < N_NODES)           g_cnt[i]  = 0.0f;
}

// Layer-1 edge scatter: agg1[dst] += x[src], cnt[dst] += 1
__global__ void k_edge1(const float* __restrict__ x,
                        const int* __restrict__ ei) {
    int e = blockIdx.x * blockDim.x + threadIdx.x;
    if (e >= N_EDGES) return;
    int s = __ldg(&ei[e]);
    int d = __ldg(&ei[N_EDGES + e]);
    const float* xs = x + (long long)s * IN_DIM;
    float* a = g_agg1 + (long long)d * IN_DIM;
    float x0 = xs[0], x1 = xs[1], x2 = xs[2], x3 = xs[3], x4 = xs[4], x5 = xs[5];
    red_add_v2(a + 0, x0, x1);
    red_add_v2(a + 2, x2, x3);
    red_add_v2(a + 4, x4, x5);
    atomicAdd(&g_cnt[d], 1.0f);
}

// Layer-1 node update: z = relu(mean @ W1_l + b1_l + x @ W1_r)
__global__ void k_node1(const float* __restrict__ x,
                        const float* __restrict__ W1l,
                        const float* __restrict__ b1l,
                        const float* __restrict__ W1r) {
    __shared__ float sWl[IN_DIM * H];
    __shared__ float sWr[IN_DIM * H];
    __shared__ float sb[H];
    int t = threadIdx.x;  // 256 threads = 4 nodes x 64 dims
    for (int i = t; i < IN_DIM * H; i += 256) { sWl[i] = W1l[i]; sWr[i] = W1r[i]; }
    if (t < H) sb[t] = b1l[t];
    __syncthreads();

    int node = blockIdx.x * 4 + (t >> 6);
    int j = t & 63;
    if (node >= N_NODES) return;

    float inv = 1.0f / fmaxf(g_cnt[node], 1.0f);
    float acc = sb[j];
    #pragma unroll
    for (int k = 0; k < IN_DIM; k++) {
        float m  = g_agg1[node * IN_DIM + k] * inv;
        float xv = x[node * IN_DIM + k];
        acc += m * sWl[k * H + j] + xv * sWr[k * H + j];
    }
    g_z[node * H + j] = fmaxf(acc, 0.0f);
}

// Layer-2 edge scatter: agg2[dst] += z[src]  (16 threads per edge, float4 lanes)
__global__ void k_edge2(const int* __restrict__ ei) {
    long long gid = (long long)blockIdx.x * blockDim.x + threadIdx.x;
    int e = (int)(gid >> 4);
    if (e >= N_EDGES) return;
    int c = (int)(gid & 15);
    int s = __ldg(&ei[e]);
    int d = __ldg(&ei[N_EDGES + e]);
    float4 v = *reinterpret_cast<const float4*>(g_z + (long long)s * H + c * 4);
    red_add_v4(g_agg2 + (long long)d * H + c * 4, v);
}

// Layer-2 node update: out = mean2 @ W2_l + b2_l + z @ W2_r
__global__ void k_node2(const float* __restrict__ W2l,
                        const float* __restrict__ b2l,
                        const float* __restrict__ W2r,
                        float* __restrict__ out) {
    __shared__ float sWl[H * H];
    __shared__ float sWr[H * H];
    __shared__ float sm[4 * H];
    __shared__ float sz[4 * H];
    int t = threadIdx.x;  // 256 threads = 4 nodes x 64 dims
    for (int i = t; i < H * H; i += 256) { sWl[i] = W2l[i]; sWr[i] = W2r[i]; }

    int node0 = blockIdx.x * 4;
    for (int i = t; i < 4 * H; i += 256) {
        int nn = node0 + (i >> 6);
        int kk = i & 63;
        float zz = 0.0f, mm = 0.0f;
        if (nn < N_NODES) {
            zz = g_z[nn * H + kk];
            mm = g_agg2[nn * H + kk] / fmaxf(g_cnt[nn], 1.0f);
        }
        sz[i] = zz; sm[i] = mm;
    }
    __syncthreads();

    int local = t >> 6;
    int j = t & 63;
    int node = node0 + local;
    if (node >= N_NODES) return;

    float acc = b2l[j];
    #pragma unroll 8
    for (int k = 0; k < H; k++) {
        acc += sm[local * H + k] * sWl[k * H + j] + sz[local * H + k] * sWr[k * H + j];
    }
    out[node * H + j] = acc;
}

extern "C" void kernel_launch(void* const* d_in, const int* in_sizes, int n_in,
                              void* d_out, int out_size) {
    const float* x   = (const float*)d_in[0];
    const int*   ei  = (const int*)d_in[1];
    const float* W1l = (const float*)d_in[2];
    const float* b1l = (const float*)d_in[3];
    const float* W1r = (const float*)d_in[4];
    const float* W2l = (const float*)d_in[5];
    const float* b2l = (const float*)d_in[6];
    const float* W2r = (const float*)d_in[7];
    float* out = (float*)d_out;

    // zero accumulators: cover N_NODES*H elements
    {
        int total = N_NODES * H;
        k_zero<<<(total + 255) / 256, 256>>>();
    }
    // layer 1
    k_edge1<<<(N_EDGES + 255) / 256, 256>>>(x, ei);
    k_node1<<<(N_NODES + 3) / 4, 256>>>(x, W1l, b1l, W1r);
    // layer 2
    {
        long long total = (long long)N_EDGES * 16;
        k_edge2<<<(unsigned)((total + 255) / 256), 256>>>(ei);
    }
    k_node2<<<(N_NODES + 3) / 4, 256>>>(W2l, b2l, W2r, out);
}